// round 5
// baseline (speedup 1.0000x reference)
#include <cuda_runtime.h>
#include <cuda_bf16.h>
#include <cstddef>

#define H      1024
#define DV     4096
#define DW     512
#define VOCAB  32000
#define NSTEP  39   // MAX_LEN - 1

// ---------------- persistent device state (no allocations allowed) ----------------
__device__ float g_h1[2][H];
__device__ float g_c1[H];
__device__ float g_h2[2][H];
__device__ float g_c2[H];
__device__ int   g_idx;
__device__ float g_norm;

__device__ __forceinline__ float sigmoidf_(float x) { return 1.0f / (1.0f + expf(-x)); }

__global__ void k_init() { g_idx = 0; }

// ---------------- LSTM1: gates = x @ w_ih^T + h @ w_hh^T + b_ih + b_hh ----------------
// One block per hidden unit j. 4 warps, one per gate (i,f,g,o rows j, j+H, j+2H, j+3H).
// x (encode only) and h_in staged in SMEM; decode has x == nullptr and skips w_ih entirely.
__global__ void k_lstm1(const float* __restrict__ w_ih, const float* __restrict__ x,
                        const float* __restrict__ w_hh,
                        const float* __restrict__ b_ih, const float* __restrict__ b_hh,
                        int pin, int pout, int c_zero)
{
    __shared__ float sh_h[H];
    __shared__ float sh_x[DV];
    __shared__ float red[4];

    const int j    = blockIdx.x;
    const int tid  = threadIdx.x;
    const int warp = tid >> 5;
    const int lane = tid & 31;

    if (pin >= 0) {
        for (int i = tid; i < H; i += 128) sh_h[i] = g_h1[pin][i];
    }
    if (x) {
        for (int i = tid; i < DV; i += 128) sh_x[i] = x[i];
    }
    __syncthreads();

    const int r = warp * H + j;   // gate row
    float s = 0.0f;
    if (pin >= 0) {
        const float4* wr = (const float4*)(w_hh + (size_t)r * H);
        const float4* hv = (const float4*)sh_h;
        #pragma unroll 4
        for (int k = lane; k < H / 4; k += 32) {
            float4 a = wr[k], b = hv[k];
            s += a.x * b.x + a.y * b.y + a.z * b.z + a.w * b.w;
        }
    }
    if (x) {
        const float4* wr = (const float4*)(w_ih + (size_t)r * DV);
        const float4* xv = (const float4*)sh_x;
        #pragma unroll 4
        for (int k = lane; k < DV / 4; k += 32) {
            float4 a = wr[k], b = xv[k];
            s += a.x * b.x + a.y * b.y + a.z * b.z + a.w * b.w;
        }
    }
    #pragma unroll
    for (int o = 16; o; o >>= 1) s += __shfl_xor_sync(0xffffffffu, s, o);
    if (lane == 0) red[warp] = s + b_ih[r] + b_hh[r];
    __syncthreads();

    if (tid == 0) {
        const float gi = red[0], gf = red[1], gg = red[2], go = red[3];
        const float cp = c_zero ? 0.0f : g_c1[j];
        const float cn = sigmoidf_(gf) * cp + sigmoidf_(gi) * tanhf(gg);
        g_c1[j]       = cn;
        g_h1[pout][j] = sigmoidf_(go) * tanhf(cn);
    }
}

// ---------------- LSTM2: input = concat(h1_new[1024], emb[g_idx][512]) ----------------
__global__ void k_lstm2(const float* __restrict__ w_ih, const float* __restrict__ w_hh,
                        const float* __restrict__ b_ih, const float* __restrict__ b_hh,
                        int p1, const float* __restrict__ emb,
                        int pin, int pout, int c_zero)
{
    __shared__ float sh_in[H + DW];
    __shared__ float sh_h2[H];
    __shared__ float red[4];

    const int j    = blockIdx.x;
    const int tid  = threadIdx.x;
    const int warp = tid >> 5;
    const int lane = tid & 31;

    for (int i = tid; i < H; i += 128) sh_in[i] = g_h1[p1][i];
    if (emb) {
        const float* wv = emb + (size_t)g_idx * DW;
        for (int i = tid; i < DW; i += 128) sh_in[H + i] = wv[i];
    } else {
        for (int i = tid; i < DW; i += 128) sh_in[H + i] = 0.0f;
    }
    if (pin >= 0) {
        for (int i = tid; i < H; i += 128) sh_h2[i] = g_h2[pin][i];
    } else {
        for (int i = tid; i < H; i += 128) sh_h2[i] = 0.0f;
    }
    __syncthreads();

    const int r = warp * H + j;
    float s = 0.0f;
    {
        const float4* wr = (const float4*)(w_ih + (size_t)r * (H + DW));
        const float4* iv = (const float4*)sh_in;
        #pragma unroll 4
        for (int k = lane; k < (H + DW) / 4; k += 32) {
            float4 a = wr[k], b = iv[k];
            s += a.x * b.x + a.y * b.y + a.z * b.z + a.w * b.w;
        }
    }
    {
        const float4* wr = (const float4*)(w_hh + (size_t)r * H);
        const float4* hv = (const float4*)sh_h2;
        #pragma unroll 4
        for (int k = lane; k < H / 4; k += 32) {
            float4 a = wr[k], b = hv[k];
            s += a.x * b.x + a.y * b.y + a.z * b.z + a.w * b.w;
        }
    }
    #pragma unroll
    for (int o = 16; o; o >>= 1) s += __shfl_xor_sync(0xffffffffu, s, o);
    if (lane == 0) red[warp] = s + b_ih[r] + b_hh[r];
    __syncthreads();

    if (tid == 0) {
        const float gi = red[0], gf = red[1], gg = red[2], go = red[3];
        const float cp = c_zero ? 0.0f : g_c2[j];
        const float cn = sigmoidf_(gf) * cp + sigmoidf_(gi) * tanhf(gg);
        g_c2[j]       = cn;
        g_h2[pout][j] = sigmoidf_(go) * tanhf(cn);
    }
}

// ---------------- logits = h2 @ w_out^T + b_out  (32000 rows, dot length 1024) ----------------
// Block = 256 threads (8 warps), 4 rows per warp -> 32 rows/block, 1000 blocks.
__global__ void k_logits(const float* __restrict__ w_out, const float* __restrict__ b_out,
                         int p2, float* __restrict__ out_t)
{
    __shared__ float sh_h[H];
    const int tid  = threadIdx.x;
    const int warp = tid >> 5;
    const int lane = tid & 31;

    for (int i = tid; i < H; i += 256) sh_h[i] = g_h2[p2][i];
    __syncthreads();

    const int r0 = blockIdx.x * 32 + warp * 4;
    const float4* hv = (const float4*)sh_h;
    const float4* w0 = (const float4*)(w_out + (size_t)(r0 + 0) * H);
    const float4* w1 = (const float4*)(w_out + (size_t)(r0 + 1) * H);
    const float4* w2 = (const float4*)(w_out + (size_t)(r0 + 2) * H);
    const float4* w3 = (const float4*)(w_out + (size_t)(r0 + 3) * H);

    float s0 = 0.f, s1 = 0.f, s2 = 0.f, s3 = 0.f;
    #pragma unroll 4
    for (int k = lane; k < H / 4; k += 32) {
        const float4 b  = hv[k];
        const float4 a0 = w0[k];
        const float4 a1 = w1[k];
        const float4 a2 = w2[k];
        const float4 a3 = w3[k];
        s0 += a0.x * b.x + a0.y * b.y + a0.z * b.z + a0.w * b.w;
        s1 += a1.x * b.x + a1.y * b.y + a1.z * b.z + a1.w * b.w;
        s2 += a2.x * b.x + a2.y * b.y + a2.z * b.z + a2.w * b.w;
        s3 += a3.x * b.x + a3.y * b.y + a3.z * b.z + a3.w * b.w;
    }
    #pragma unroll
    for (int o = 16; o; o >>= 1) {
        s0 += __shfl_xor_sync(0xffffffffu, s0, o);
        s1 += __shfl_xor_sync(0xffffffffu, s1, o);
        s2 += __shfl_xor_sync(0xffffffffu, s2, o);
        s3 += __shfl_xor_sync(0xffffffffu, s3, o);
    }
    if (lane == 0) {
        out_t[r0 + 0] = s0 + b_out[r0 + 0];
        out_t[r0 + 1] = s1 + b_out[r0 + 1];
        out_t[r0 + 2] = s2 + b_out[r0 + 2];
        out_t[r0 + 3] = s3 + b_out[r0 + 3];
    }
}

// ---------------- log-sum-exp over 32000 logits (streaming) + argmax over h2 ----------------
__global__ void k_lse(const float* __restrict__ logits, int p2)
{
    __shared__ float sm[1024];
    __shared__ float ss[1024];
    __shared__ int   si[1024];
    const int tid = threadIdx.x;

    // streaming (max, sum-exp) per thread; every thread sees >= 31 elements
    float m = -3.4e38f, s = 0.0f;
    for (int i = tid; i < VOCAB; i += 1024) {
        const float v = logits[i];
        if (v > m) { s = s * expf(m - v) + 1.0f; m = v; }
        else       { s += expf(v - m); }
    }
    sm[tid] = m; ss[tid] = s;
    __syncthreads();
    for (int off = 512; off; off >>= 1) {
        if (tid < off) {
            const float m1 = sm[tid], s1 = ss[tid];
            const float m2 = sm[tid + off], s2 = ss[tid + off];
            if (m2 > m1) { sm[tid] = m2; ss[tid] = s2 + s1 * expf(m1 - m2); }
            else         { ss[tid] = s1 + s2 * expf(m2 - m1); }
        }
        __syncthreads();
    }
    if (tid == 0) g_norm = sm[0] + logf(ss[0]);
    __syncthreads();

    // argmax over h2 (1024 values), first-index tie-break (matches jnp.argmax)
    sm[tid] = g_h2[p2][tid];
    si[tid] = tid;
    __syncthreads();
    for (int off = 512; off; off >>= 1) {
        if (tid < off) {
            const float v2 = sm[tid + off];
            const int   i2 = si[tid + off];
            if (v2 > sm[tid] || (v2 == sm[tid] && i2 < si[tid])) { sm[tid] = v2; si[tid] = i2; }
        }
        __syncthreads();
    }
    if (tid == 0) g_idx = si[0];
}

// ---------------- normalize: logp = logits - (max + log(sumexp)) ----------------
__global__ void k_norm(float* __restrict__ out_t)
{
    const int i = blockIdx.x * 256 + threadIdx.x;
    if (i < VOCAB) out_t[i] -= g_norm;
}

// ---------------- host driver (graph-capturable: kernel launches only) ----------------
extern "C" void kernel_launch(void* const* d_in, const int* in_sizes, int n_in,
                              void* d_out, int out_size)
{
    const float* vid   = (const float*)d_in[0];
    const float* w_ih1 = (const float*)d_in[1];
    const float* w_hh1 = (const float*)d_in[2];
    const float* b_ih1 = (const float*)d_in[3];
    const float* b_hh1 = (const float*)d_in[4];
    const float* w_ih2 = (const float*)d_in[5];
    const float* w_hh2 = (const float*)d_in[6];
    const float* b_ih2 = (const float*)d_in[7];
    const float* b_hh2 = (const float*)d_in[8];
    const float* emb   = (const float*)d_in[9];
    const float* w_out = (const float*)d_in[10];
    const float* b_out = (const float*)d_in[11];
    float* out = (float*)d_out;

    (void)in_sizes; (void)n_in; (void)out_size;

    k_init<<<1, 1>>>();

    // encode: LSTM1(vid, h=0, c=0) -> h1,c1 ; LSTM2([h1, zeros], h=0, c=0) -> h2,c2
    k_lstm1<<<H, 128>>>(w_ih1, vid, w_hh1, b_ih1, b_hh1, /*pin=*/-1, /*pout=*/0, /*c_zero=*/1);
    k_lstm2<<<H, 128>>>(w_ih2, w_hh2, b_ih2, b_hh2, /*p1=*/0, /*emb=*/nullptr,
                        /*pin=*/-1, /*pout=*/0, /*c_zero=*/1);

    for (int t = 0; t < NSTEP; t++) {
        const int pin  = t & 1;
        const int pout = 1 - pin;
        float* out_t = out + (size_t)t * VOCAB;

        // LSTM1 with zero input (pad_vid): only the recurrent matvec
        k_lstm1<<<H, 128>>>(nullptr, nullptr, w_hh1, b_ih1, b_hh1, pin, pout, 0);
        // LSTM2 with [h1_new, emb[g_idx]]
        k_lstm2<<<H, 128>>>(w_ih2, w_hh2, b_ih2, b_hh2, pout, emb, pin, pout, 0);
        // logits + bias
        k_logits<<<VOCAB / 32, 256>>>(w_out, b_out, pout, out_t);
        // logsumexp + argmax(h2) -> next token index
        k_lse<<<1, 1024>>>(out_t, pout);
        // in-place log-softmax
        k_norm<<<(VOCAB + 255) / 256, 256>>>(out_t);
    }
}

// round 6
// speedup vs baseline: 2.2027x; 2.2027x over previous
#include <cuda_runtime.h>
#include <cuda_bf16.h>
#include <cstddef>
#include <cstdint>

#define H      1024
#define DV     4096
#define DW     512
#define VOCAB  32000
#define NSTEP  39   // MAX_LEN - 1

// ---------------- persistent device state (no allocations allowed) ----------------
__device__ float g_h1[2][H];
__device__ float g_c1[H];
__device__ float g_h2[2][H];
__device__ float g_c2[H];
__device__ int   g_idx;

// int8 output-projection cache (built once per launch)
__device__ int   g_wq[VOCAB * (H / 4)];   // packed 4x s8 per word, 32.77 MB
__device__ float g_wscale[VOCAB];         // per-row scale
__device__ int4  g_qh[2][H / 16];         // quantized h2 (page-indexed), packed s8
__device__ float g_hscale[2];             // h2 scale per page

__device__ __forceinline__ float sigmoidf_(float x) { return 1.0f / (1.0f + expf(-x)); }

__global__ void k_init() { g_idx = 0; }

// ---------------- quantize w_out rows to int8 (runs once per launch, off critical path) ----------------
// grid 1000 x 256: 8 warps/block, 4 rows/warp.
__global__ void k_quant_w(const float* __restrict__ w)
{
    const int warp = threadIdx.x >> 5;
    const int lane = threadIdx.x & 31;
    const int row0 = blockIdx.x * 32 + warp * 4;

    for (int rr = 0; rr < 4; rr++) {
        const int row = row0 + rr;
        const float4* wr = (const float4*)(w + (size_t)row * H);
        float4 v[8];
        float m = 0.0f;
        #pragma unroll
        for (int i = 0; i < 8; i++) {
            v[i] = wr[lane + 32 * i];
            m = fmaxf(m, fmaxf(fmaxf(fabsf(v[i].x), fabsf(v[i].y)),
                               fmaxf(fabsf(v[i].z), fabsf(v[i].w))));
        }
        #pragma unroll
        for (int o = 16; o; o >>= 1) m = fmaxf(m, __shfl_xor_sync(0xffffffffu, m, o));
        const float inv = (m > 0.0f) ? 127.0f / m : 0.0f;
        #pragma unroll
        for (int i = 0; i < 8; i++) {
            const int a = (int)rintf(v[i].x * inv);
            const int b = (int)rintf(v[i].y * inv);
            const int c = (int)rintf(v[i].z * inv);
            const int d = (int)rintf(v[i].w * inv);
            g_wq[row * (H / 4) + lane + 32 * i] =
                (a & 0xFF) | ((b & 0xFF) << 8) | ((c & 0xFF) << 16) | ((d & 0xFF) << 24);
        }
        if (lane == 0) g_wscale[row] = m / 127.0f;
    }
}

// ---------------- LSTM1 encode: gates = vid @ w_ih^T + b_ih + b_hh, h=c=0 ----------------
__global__ void k_lstm1_enc(const float* __restrict__ w_ih, const float* __restrict__ x,
                            const float* __restrict__ b_ih, const float* __restrict__ b_hh)
{
    __shared__ float sx[DV];
    __shared__ float red[4];
    const int j = blockIdx.x, tid = threadIdx.x, warp = tid >> 5, lane = tid & 31;

    for (int i = tid; i < DV; i += 128) sx[i] = x[i];
    __syncthreads();

    const int r = warp * H + j;
    const float4* wr = (const float4*)(w_ih + (size_t)r * DV);
    const float4* xv = (const float4*)sx;
    float s0 = 0.f, s1 = 0.f, s2 = 0.f, s3 = 0.f;
    #pragma unroll
    for (int k0 = 0; k0 < DV / 4; k0 += 128) {
        float4 a, b;
        a = wr[k0 + lane];      b = xv[k0 + lane];      s0 += a.x*b.x + a.y*b.y + a.z*b.z + a.w*b.w;
        a = wr[k0 + lane + 32]; b = xv[k0 + lane + 32]; s1 += a.x*b.x + a.y*b.y + a.z*b.z + a.w*b.w;
        a = wr[k0 + lane + 64]; b = xv[k0 + lane + 64]; s2 += a.x*b.x + a.y*b.y + a.z*b.z + a.w*b.w;
        a = wr[k0 + lane + 96]; b = xv[k0 + lane + 96]; s3 += a.x*b.x + a.y*b.y + a.z*b.z + a.w*b.w;
    }
    float s = (s0 + s1) + (s2 + s3);
    #pragma unroll
    for (int o = 16; o; o >>= 1) s += __shfl_xor_sync(0xffffffffu, s, o);
    if (lane == 0) red[warp] = s + b_ih[r] + b_hh[r];
    __syncthreads();

    if (tid == 0) {
        const float gi = red[0], gf = red[1], gg = red[2], go = red[3];
        const float cn = sigmoidf_(gi) * tanhf(gg);   // c_prev = 0
        g_c1[j]     = cn;
        g_h1[0][j]  = sigmoidf_(go) * tanhf(cn);
    }
}

// ---------------- LSTM1 decode: x = 0, only the recurrent matvec ----------------
__global__ void k_lstm1_dec(const float* __restrict__ w_hh,
                            const float* __restrict__ b_ih, const float* __restrict__ b_hh,
                            int pin, int pout)
{
    __shared__ float sh[H];
    __shared__ float red[4];
    const int j = blockIdx.x, tid = threadIdx.x, warp = tid >> 5, lane = tid & 31;

    for (int i = tid; i < H; i += 128) sh[i] = g_h1[pin][i];
    __syncthreads();

    const int r = warp * H + j;
    const float4* wr = (const float4*)(w_hh + (size_t)r * H);
    const float4* hv = (const float4*)sh;
    float s0 = 0.f, s1 = 0.f, s2 = 0.f, s3 = 0.f;
    #pragma unroll
    for (int k0 = 0; k0 < H / 4; k0 += 128) {
        float4 a, b;
        a = wr[k0 + lane];      b = hv[k0 + lane];      s0 += a.x*b.x + a.y*b.y + a.z*b.z + a.w*b.w;
        a = wr[k0 + lane + 32]; b = hv[k0 + lane + 32]; s1 += a.x*b.x + a.y*b.y + a.z*b.z + a.w*b.w;
        a = wr[k0 + lane + 64]; b = hv[k0 + lane + 64]; s2 += a.x*b.x + a.y*b.y + a.z*b.z + a.w*b.w;
        a = wr[k0 + lane + 96]; b = hv[k0 + lane + 96]; s3 += a.x*b.x + a.y*b.y + a.z*b.z + a.w*b.w;
    }
    float s = (s0 + s1) + (s2 + s3);
    #pragma unroll
    for (int o = 16; o; o >>= 1) s += __shfl_xor_sync(0xffffffffu, s, o);
    if (lane == 0) red[warp] = s + b_ih[r] + b_hh[r];
    __syncthreads();

    if (tid == 0) {
        const float gi = red[0], gf = red[1], gg = red[2], go = red[3];
        const float cn = sigmoidf_(gf) * g_c1[j] + sigmoidf_(gi) * tanhf(gg);
        g_c1[j]       = cn;
        g_h1[pout][j] = sigmoidf_(go) * tanhf(cn);
    }
}

// ---------------- LSTM2: input = concat(h1[p1], emb[g_idx] or zeros) ----------------
__global__ void k_lstm2(const float* __restrict__ w_ih, const float* __restrict__ w_hh,
                        const float* __restrict__ b_ih, const float* __restrict__ b_hh,
                        int p1, const float* __restrict__ emb,
                        int pin, int pout)
{
    __shared__ float sh_in[H + DW];
    __shared__ float sh_h2[H];
    __shared__ float red[4];
    const int j = blockIdx.x, tid = threadIdx.x, warp = tid >> 5, lane = tid & 31;

    for (int i = tid; i < H; i += 128) sh_in[i] = g_h1[p1][i];
    if (emb) {
        const float* wv = emb + (size_t)g_idx * DW;
        for (int i = tid; i < DW; i += 128) sh_in[H + i] = wv[i];
    } else {
        for (int i = tid; i < DW; i += 128) sh_in[H + i] = 0.0f;
    }
    if (pin >= 0) {
        for (int i = tid; i < H; i += 128) sh_h2[i] = g_h2[pin][i];
    } else {
        for (int i = tid; i < H; i += 128) sh_h2[i] = 0.0f;
    }
    __syncthreads();

    const int r = warp * H + j;
    float s0 = 0.f, s1 = 0.f, s2 = 0.f, s3 = 0.f;
    {
        const float4* wr = (const float4*)(w_ih + (size_t)r * (H + DW));
        const float4* iv = (const float4*)sh_in;
        #pragma unroll
        for (int k0 = 0; k0 < (H + DW) / 4; k0 += 128) {
            float4 a, b;
            a = wr[k0 + lane];      b = iv[k0 + lane];      s0 += a.x*b.x + a.y*b.y + a.z*b.z + a.w*b.w;
            a = wr[k0 + lane + 32]; b = iv[k0 + lane + 32]; s1 += a.x*b.x + a.y*b.y + a.z*b.z + a.w*b.w;
            a = wr[k0 + lane + 64]; b = iv[k0 + lane + 64]; s2 += a.x*b.x + a.y*b.y + a.z*b.z + a.w*b.w;
            a = wr[k0 + lane + 96]; b = iv[k0 + lane + 96]; s3 += a.x*b.x + a.y*b.y + a.z*b.z + a.w*b.w;
        }
    }
    {
        const float4* wr = (const float4*)(w_hh + (size_t)r * H);
        const float4* hv = (const float4*)sh_h2;
        #pragma unroll
        for (int k0 = 0; k0 < H / 4; k0 += 128) {
            float4 a, b;
            a = wr[k0 + lane];      b = hv[k0 + lane];      s0 += a.x*b.x + a.y*b.y + a.z*b.z + a.w*b.w;
            a = wr[k0 + lane + 32]; b = hv[k0 + lane + 32]; s1 += a.x*b.x + a.y*b.y + a.z*b.z + a.w*b.w;
            a = wr[k0 + lane + 64]; b = hv[k0 + lane + 64]; s2 += a.x*b.x + a.y*b.y + a.z*b.z + a.w*b.w;
            a = wr[k0 + lane + 96]; b = hv[k0 + lane + 96]; s3 += a.x*b.x + a.y*b.y + a.z*b.z + a.w*b.w;
        }
    }
    float s = (s0 + s1) + (s2 + s3);
    #pragma unroll
    for (int o = 16; o; o >>= 1) s += __shfl_xor_sync(0xffffffffu, s, o);
    if (lane == 0) red[warp] = s + b_ih[r] + b_hh[r];
    __syncthreads();

    if (tid == 0) {
        const float gi = red[0], gf = red[1], gg = red[2], go = red[3];
        const float cp = (pin >= 0) ? g_c2[j] : 0.0f;
        const float cn = sigmoidf_(gf) * cp + sigmoidf_(gi) * tanhf(gg);
        g_c2[j]       = cn;
        g_h2[pout][j] = sigmoidf_(go) * tanhf(cn);
    }
}

// ---------------- h2 post: argmax (-> g_idx), absmax, int8-quantize h2 ----------------
__global__ void k_h2prep(int page)
{
    __shared__ float sv[1024];
    __shared__ int   si[1024];
    __shared__ float sa[1024];
    __shared__ int   sq[1024];
    __shared__ float s_inv;
    const int tid = threadIdx.x;

    const float v = g_h2[page][tid];
    sv[tid] = v; si[tid] = tid; sa[tid] = fabsf(v);
    __syncthreads();
    for (int off = 512; off; off >>= 1) {
        if (tid < off) {
            const float v2 = sv[tid + off];
            const int   i2 = si[tid + off];
            if (v2 > sv[tid] || (v2 == sv[tid] && i2 < si[tid])) { sv[tid] = v2; si[tid] = i2; }
            sa[tid] = fmaxf(sa[tid], sa[tid + off]);
        }
        __syncthreads();
    }
    if (tid == 0) {
        g_idx = si[0];
        const float m = sa[0];
        g_hscale[page] = m / 127.0f;
        s_inv = (m > 0.0f) ? 127.0f / m : 0.0f;
    }
    __syncthreads();

    sq[tid] = ((int)rintf(v * s_inv)) & 0xFF;
    __syncthreads();
    if (tid < H / 4) {
        ((int*)g_qh[page])[tid] = sq[4 * tid] | (sq[4 * tid + 1] << 8) |
                                  (sq[4 * tid + 2] << 16) | (sq[4 * tid + 3] << 24);
    }
}

// ---------------- int8 logits: out = (sw * sh) * dp4a(wq, qh) + b_out ----------------
// grid 1000, block 256 (8 warps x 4 rows).
__global__ void k_logits_q(const float* __restrict__ b_out, int page, float* __restrict__ out_t)
{
    __shared__ int4 shq[H / 16];   // 64 x int4 = 256 words
    const int tid = threadIdx.x, warp = tid >> 5, lane = tid & 31;

    if (tid < H / 16) shq[tid] = g_qh[page][tid];
    __syncthreads();

    const float sh = g_hscale[page];
    const int r0 = blockIdx.x * 32 + warp * 4;
    const int4* w0 = (const int4*)(g_wq + (size_t)(r0 + 0) * (H / 4));
    const int4* w1 = (const int4*)(g_wq + (size_t)(r0 + 1) * (H / 4));
    const int4* w2 = (const int4*)(g_wq + (size_t)(r0 + 2) * (H / 4));
    const int4* w3 = (const int4*)(g_wq + (size_t)(r0 + 3) * (H / 4));

    int s0 = 0, s1 = 0, s2 = 0, s3 = 0;
    #pragma unroll
    for (int k = lane; k < H / 16; k += 32) {   // 2 iterations
        const int4 h = shq[k];
        int4 a;
        a = w0[k]; s0 = __dp4a(a.x, h.x, s0); s0 = __dp4a(a.y, h.y, s0);
                   s0 = __dp4a(a.z, h.z, s0); s0 = __dp4a(a.w, h.w, s0);
        a = w1[k]; s1 = __dp4a(a.x, h.x, s1); s1 = __dp4a(a.y, h.y, s1);
                   s1 = __dp4a(a.z, h.z, s1); s1 = __dp4a(a.w, h.w, s1);
        a = w2[k]; s2 = __dp4a(a.x, h.x, s2); s2 = __dp4a(a.y, h.y, s2);
                   s2 = __dp4a(a.z, h.z, s2); s2 = __dp4a(a.w, h.w, s2);
        a = w3[k]; s3 = __dp4a(a.x, h.x, s3); s3 = __dp4a(a.y, h.y, s3);
                   s3 = __dp4a(a.z, h.z, s3); s3 = __dp4a(a.w, h.w, s3);
    }
    s0 = __reduce_add_sync(0xffffffffu, s0);
    s1 = __reduce_add_sync(0xffffffffu, s1);
    s2 = __reduce_add_sync(0xffffffffu, s2);
    s3 = __reduce_add_sync(0xffffffffu, s3);
    if (lane == 0) {
        out_t[r0 + 0] = g_wscale[r0 + 0] * sh * (float)s0 + b_out[r0 + 0];
        out_t[r0 + 1] = g_wscale[r0 + 1] * sh * (float)s1 + b_out[r0 + 1];
        out_t[r0 + 2] = g_wscale[r0 + 2] * sh * (float)s2 + b_out[r0 + 2];
        out_t[r0 + 3] = g_wscale[r0 + 3] * sh * (float)s3 + b_out[r0 + 3];
    }
}

// ---------------- fused log-sum-exp + in-place log-softmax (1 block) ----------------
__global__ void k_lsenorm(float* __restrict__ out_t)
{
    __shared__ float sm[1024];
    __shared__ float ss[1024];
    __shared__ float s_norm;
    const int tid = threadIdx.x;

    float m = -3.0e38f, s = 0.0f;
    float4* p = (float4*)out_t;
    for (int i = tid; i < VOCAB / 4; i += 1024) {
        const float4 v = p[i];
        const float vv[4] = {v.x, v.y, v.z, v.w};
        #pragma unroll
        for (int u = 0; u < 4; u++) {
            const float x = vv[u];
            if (x > m) { s = s * __expf(m - x) + 1.0f; m = x; }
            else       { s += __expf(x - m); }
        }
    }
    sm[tid] = m; ss[tid] = s;
    __syncthreads();
    for (int off = 512; off; off >>= 1) {
        if (tid < off) {
            const float m1 = sm[tid], s1 = ss[tid];
            const float m2 = sm[tid + off], s2 = ss[tid + off];
            if (m2 > m1) { sm[tid] = m2; ss[tid] = s2 + s1 * __expf(m1 - m2); }
            else         { ss[tid] = s1 + s2 * __expf(m2 - m1); }
        }
        __syncthreads();
    }
    if (tid == 0) s_norm = sm[0] + logf(ss[0]);
    __syncthreads();

    const float n = s_norm;
    for (int i = tid; i < VOCAB / 4; i += 1024) {
        float4 v = p[i];
        v.x -= n; v.y -= n; v.z -= n; v.w -= n;
        p[i] = v;
    }
}

// ---------------- host driver: two-stream pipeline, graph-capturable ----------------
extern "C" void kernel_launch(void* const* d_in, const int* in_sizes, int n_in,
                              void* d_out, int out_size)
{
    const float* vid   = (const float*)d_in[0];
    const float* w_ih1 = (const float*)d_in[1];
    const float* w_hh1 = (const float*)d_in[2];
    const float* b_ih1 = (const float*)d_in[3];
    const float* b_hh1 = (const float*)d_in[4];
    const float* w_ih2 = (const float*)d_in[5];
    const float* w_hh2 = (const float*)d_in[6];
    const float* b_ih2 = (const float*)d_in[7];
    const float* b_hh2 = (const float*)d_in[8];
    const float* emb   = (const float*)d_in[9];
    const float* w_out = (const float*)d_in[10];
    const float* b_out = (const float*)d_in[11];
    float* out = (float*)d_out;

    (void)in_sizes; (void)n_in; (void)out_size;

    // Host-side stream/event objects, created once on the first (non-capturing)
    // correctness call. No device memory is allocated here.
    static cudaStream_t sB = nullptr;
    static cudaEvent_t  evMain[NSTEP], evB[NSTEP], evStart;
    if (!sB) {
        cudaStreamCreateWithFlags(&sB, cudaStreamNonBlocking);
        cudaEventCreateWithFlags(&evStart, cudaEventDisableTiming);
        for (int i = 0; i < NSTEP; i++) {
            cudaEventCreateWithFlags(&evMain[i], cudaEventDisableTiming);
            cudaEventCreateWithFlags(&evB[i],    cudaEventDisableTiming);
        }
    }

    k_init<<<1, 1>>>();

    // Fork side stream; build the int8 w_out cache there, overlapped with encode.
    cudaEventRecord(evStart, 0);
    cudaStreamWaitEvent(sB, evStart, 0);
    k_quant_w<<<VOCAB / 32, 256, 0, sB>>>(w_out);

    // encode on main stream
    k_lstm1_enc<<<H, 128>>>(w_ih1, vid, b_ih1, b_hh1);
    k_lstm2<<<H, 128>>>(w_ih2, w_hh2, b_ih2, b_hh2, /*p1=*/0, /*emb=*/nullptr,
                        /*pin=*/-1, /*pout=*/0);

    for (int t = 0; t < NSTEP; t++) {
        const int pin  = t & 1;
        const int pout = 1 - pin;
        float* out_t = out + (size_t)t * VOCAB;

        // page-reuse guard: h2prep(t) rewrites q_h2 page used by logits(t-2)
        if (t >= 2) cudaStreamWaitEvent(0, evB[t - 2], 0);

        // recurrence path (main stream)
        k_lstm1_dec<<<H, 128>>>(w_hh1, b_ih1, b_hh1, pin, pout);
        k_lstm2<<<H, 128>>>(w_ih2, w_hh2, b_ih2, b_hh2, pout, emb, pin, pout);
        k_h2prep<<<1, 1024>>>(pout);
        cudaEventRecord(evMain[t], 0);

        // output path (side stream), overlapped with next step's recurrence
        cudaStreamWaitEvent(sB, evMain[t], 0);
        k_logits_q<<<VOCAB / 32, 256, 0, sB>>>(b_out, pout, out_t);
        k_lsenorm<<<1, 1024, 0, sB>>>(out_t);
        cudaEventRecord(evB[t], sB);
    }

    // join side stream back into the origin stream before capture ends
    cudaStreamWaitEvent(0, evB[NSTEP - 1], 0);
}

// round 9
// speedup vs baseline: 2.4633x; 1.1183x over previous
#include <cuda_runtime.h>
#include <cuda_bf16.h>
#include <cstddef>
#include <cstdint>

#define H      1024
#define DV     4096
#define DW     512
#define VOCAB  32000
#define NSTEP  39   // MAX_LEN - 1

// ---------------- persistent device state (no allocations allowed) ----------------
__device__ float g_h1[2][H];
__device__ float g_c1[H];
__device__ float g_h2[2][H];
__device__ float g_c2[H];
__device__ int   g_idx;

__device__ float g_p1[2][4 * H];   // lstm1 split-K partials [half][gate-row]
__device__ float g_p2[4 * H];      // lstm2 independent-part partials [gate-row]

// int8 output-projection cache (built once per launch)
__device__ int   g_wq[VOCAB * (H / 4)];   // packed 4x s8 per word, 32.77 MB
__device__ float g_wscale[VOCAB];
__device__ int4  g_qh[2][H / 16];
__device__ float g_hscale[2];

__device__ __forceinline__ float sigmoidf_(float x) { return 1.0f / (1.0f + expf(-x)); }

__global__ void k_init() { g_idx = 0; }

// ---------------- quantize w_out rows to int8 (once per launch, side stream) ----------------
__global__ void k_quant_w(const float* __restrict__ w)
{
    const int warp = threadIdx.x >> 5;
    const int lane = threadIdx.x & 31;
    const int row0 = blockIdx.x * 32 + warp * 4;

    for (int rr = 0; rr < 4; rr++) {
        const int row = row0 + rr;
        const float4* wr = (const float4*)(w + (size_t)row * H);
        float4 v[8];
        float m = 0.0f;
        #pragma unroll
        for (int i = 0; i < 8; i++) {
            v[i] = wr[lane + 32 * i];
            m = fmaxf(m, fmaxf(fmaxf(fabsf(v[i].x), fabsf(v[i].y)),
                               fmaxf(fabsf(v[i].z), fabsf(v[i].w))));
        }
        #pragma unroll
        for (int o = 16; o; o >>= 1) m = fmaxf(m, __shfl_xor_sync(0xffffffffu, m, o));
        const float inv = (m > 0.0f) ? 127.0f / m : 0.0f;
        #pragma unroll
        for (int i = 0; i < 8; i++) {
            const int a = (int)rintf(v[i].x * inv);
            const int b = (int)rintf(v[i].y * inv);
            const int c = (int)rintf(v[i].z * inv);
            const int d = (int)rintf(v[i].w * inv);
            g_wq[row * (H / 4) + lane + 32 * i] =
                (a & 0xFF) | ((b & 0xFF) << 8) | ((c & 0xFF) << 16) | ((d & 0xFF) << 24);
        }
        if (lane == 0) g_wscale[row] = m / 127.0f;
    }
}

// ---------------- LSTM1 encode: gates = vid @ w_ih^T + b_ih + b_hh (h=c=0) ----------------
__global__ void k_lstm1_enc(const float* __restrict__ w_ih, const float* __restrict__ x,
                            const float* __restrict__ b_ih, const float* __restrict__ b_hh)
{
    __shared__ float sx[DV];
    __shared__ float red[4];
    const int j = blockIdx.x, tid = threadIdx.x, warp = tid >> 5, lane = tid & 31;

    for (int i = tid; i < DV; i += 128) sx[i] = x[i];
    __syncthreads();

    const int r = warp * H + j;
    const float4* wr = (const float4*)(w_ih + (size_t)r * DV);
    const float4* xv = (const float4*)sx;
    float s = 0.0f;
    #pragma unroll
    for (int k0 = 0; k0 < DV / 4; k0 += 256) {
        float4 a[8];
        #pragma unroll
        for (int u = 0; u < 8; u++) a[u] = wr[k0 + lane + 32 * u];
        #pragma unroll
        for (int u = 0; u < 8; u++) {
            const float4 b = xv[k0 + lane + 32 * u];
            s += a[u].x * b.x + a[u].y * b.y + a[u].z * b.z + a[u].w * b.w;
        }
    }
    #pragma unroll
    for (int o = 16; o; o >>= 1) s += __shfl_xor_sync(0xffffffffu, s, o);
    if (lane == 0) red[warp] = s + b_ih[r] + b_hh[r];
    __syncthreads();

    if (tid == 0) {
        const float gi = red[0], gf = red[1], gg = red[2], go = red[3];
        const float cn = sigmoidf_(gi) * tanhf(gg);
        g_c1[j]    = cn;
        g_h1[0][j] = sigmoidf_(go) * tanhf(cn);
    }
}

// ---------------- fused partials: blocks [0,2048) lstm1 split-K, [2048,3072) lstm2-independent ----
// Everything here depends only on end-of-step(t-1) state (h1[pin], h2[pin], g_idx),
// so a single launch runs both matvecs concurrently across the whole chip.
__global__ void k_part(const float* __restrict__ w_hh1,
                       const float* __restrict__ w_ih2, const float* __restrict__ w_hh2,
                       const float* __restrict__ emb, int pin)
{
    __shared__ float sv[H + DW];   // max of the two staging needs
    const int tid = threadIdx.x, warp = tid >> 5, lane = tid & 31;

    if (blockIdx.x < 2 * H) {
        // ---- lstm1 partial: half of the K dimension ----
        const int j    = blockIdx.x & (H - 1);
        const int half = blockIdx.x >> 10;

        for (int i = tid; i < H / 2; i += 128) sv[i] = g_h1[pin][half * (H / 2) + i];
        __syncthreads();

        const int r = warp * H + j;
        const float4* wr = (const float4*)(w_hh1 + (size_t)r * H + half * (H / 2));
        const float4* hv = (const float4*)sv;
        float4 a[4];
        #pragma unroll
        for (int u = 0; u < 4; u++) a[u] = wr[lane + 32 * u];
        float s = 0.0f;
        #pragma unroll
        for (int u = 0; u < 4; u++) {
            const float4 b = hv[lane + 32 * u];
            s += a[u].x * b.x + a[u].y * b.y + a[u].z * b.z + a[u].w * b.w;
        }
        #pragma unroll
        for (int o = 16; o; o >>= 1) s += __shfl_xor_sync(0xffffffffu, s, o);
        if (lane == 0) g_p1[half][r] = s;
    } else {
        // ---- lstm2 independent part: w_hh2*h2_prev + w_ih2[:,1024:]*emb[g_idx] ----
        const int j = blockIdx.x - 2 * H;

        for (int i = tid; i < H; i += 128) sv[i] = g_h2[pin][i];
        {
            const float* wv = emb + (size_t)g_idx * DW;
            for (int i = tid; i < DW; i += 128) sv[H + i] = wv[i];
        }
        __syncthreads();

        const int r = warp * H + j;
        const float4* whh  = (const float4*)(w_hh2 + (size_t)r * H);
        const float4* wemb = (const float4*)(w_ih2 + (size_t)r * (H + DW) + H);
        const float4* hv   = (const float4*)sv;

        float4 a[8], e[4];
        #pragma unroll
        for (int u = 0; u < 8; u++) a[u] = whh[lane + 32 * u];
        #pragma unroll
        for (int u = 0; u < 4; u++) e[u] = wemb[lane + 32 * u];

        float s = 0.0f;
        #pragma unroll
        for (int u = 0; u < 8; u++) {
            const float4 b = hv[lane + 32 * u];
            s += a[u].x * b.x + a[u].y * b.y + a[u].z * b.z + a[u].w * b.w;
        }
        #pragma unroll
        for (int u = 0; u < 4; u++) {
            const float4 b = hv[H / 4 + lane + 32 * u];
            s += e[u].x * b.x + e[u].y * b.y + e[u].z * b.z + e[u].w * b.w;
        }
        #pragma unroll
        for (int o = 16; o; o >>= 1) s += __shfl_xor_sync(0xffffffffu, s, o);
        if (lane == 0) g_p2[r] = s;
    }
}

// ---------------- LSTM1 finish: combine partials, gate, write h1/c1 ----------------
__global__ void k_l1fin(const float* __restrict__ b_ih, const float* __restrict__ b_hh, int pout)
{
    const int j = blockIdx.x * 128 + threadIdx.x;
    const int ri = j, rf = j + H, rg = j + 2 * H, ro = j + 3 * H;
    const float gi = g_p1[0][ri] + g_p1[1][ri] + b_ih[ri] + b_hh[ri];
    const float gf = g_p1[0][rf] + g_p1[1][rf] + b_ih[rf] + b_hh[rf];
    const float gg = g_p1[0][rg] + g_p1[1][rg] + b_ih[rg] + b_hh[rg];
    const float go = g_p1[0][ro] + g_p1[1][ro] + b_ih[ro] + b_hh[ro];
    const float cn = sigmoidf_(gf) * g_c1[j] + sigmoidf_(gi) * tanhf(gg);
    g_c1[j]       = cn;
    g_h1[pout][j] = sigmoidf_(go) * tanhf(cn);
}

// ---------------- LSTM2 dependent part: w_ih2[:,0:1024]*h1_new (+ partial), gate ----------------
__global__ void k_l2dep(const float* __restrict__ w_ih,
                        const float* __restrict__ b_ih, const float* __restrict__ b_hh,
                        int p1, int pout, int use_part, int c_zero)
{
    __shared__ float sh[H];
    __shared__ float red[4];
    const int j = blockIdx.x, tid = threadIdx.x, warp = tid >> 5, lane = tid & 31;

    for (int i = tid; i < H; i += 128) sh[i] = g_h1[p1][i];
    __syncthreads();

    const int r = warp * H + j;
    const float4* wr = (const float4*)(w_ih + (size_t)r * (H + DW));
    const float4* hv = (const float4*)sh;
    float4 a[8];
    #pragma unroll
    for (int u = 0; u < 8; u++) a[u] = wr[lane + 32 * u];
    float s = 0.0f;
    #pragma unroll
    for (int u = 0; u < 8; u++) {
        const float4 b = hv[lane + 32 * u];
        s += a[u].x * b.x + a[u].y * b.y + a[u].z * b.z + a[u].w * b.w;
    }
    #pragma unroll
    for (int o = 16; o; o >>= 1) s += __shfl_xor_sync(0xffffffffu, s, o);
    if (lane == 0) {
        float g = s + b_ih[r] + b_hh[r];
        if (use_part) g += g_p2[r];
        red[warp] = g;
    }
    __syncthreads();

    if (tid == 0) {
        const float gi = red[0], gf = red[1], gg = red[2], go = red[3];
        const float cp = c_zero ? 0.0f : g_c2[j];
        const float cn = sigmoidf_(gf) * cp + sigmoidf_(gi) * tanhf(gg);
        g_c2[j]       = cn;
        g_h2[pout][j] = sigmoidf_(go) * tanhf(cn);
    }
}

// ---------------- h2 post: argmax -> g_idx, absmax, int8-quantize h2 ----------------
__global__ void k_h2prep(int page)
{
    __shared__ float sv[1024];
    __shared__ int   si[1024];
    __shared__ float sa[1024];
    __shared__ int   sq[1024];
    __shared__ float s_inv;
    const int tid = threadIdx.x;

    const float v = g_h2[page][tid];
    sv[tid] = v; si[tid] = tid; sa[tid] = fabsf(v);
    __syncthreads();
    for (int off = 512; off; off >>= 1) {
        if (tid < off) {
            const float v2 = sv[tid + off];
            const int   i2 = si[tid + off];
            if (v2 > sv[tid] || (v2 == sv[tid] && i2 < si[tid])) { sv[tid] = v2; si[tid] = i2; }
            sa[tid] = fmaxf(sa[tid], sa[tid + off]);
        }
        __syncthreads();
    }
    if (tid == 0) {
        g_idx = si[0];
        const float m = sa[0];
        g_hscale[page] = m / 127.0f;
        s_inv = (m > 0.0f) ? 127.0f / m : 0.0f;
    }
    __syncthreads();

    sq[tid] = ((int)rintf(v * s_inv)) & 0xFF;
    __syncthreads();
    if (tid < H / 4) {
        ((int*)g_qh[page])[tid] = sq[4 * tid] | (sq[4 * tid + 1] << 8) |
                                  (sq[4 * tid + 2] << 16) | (sq[4 * tid + 3] << 24);
    }
}

// ---------------- int8 logits ----------------
__global__ void k_logits_q(const float* __restrict__ b_out, int page, float* __restrict__ out_t)
{
    __shared__ int4 shq[H / 16];
    const int tid = threadIdx.x, warp = tid >> 5, lane = tid & 31;

    if (tid < H / 16) shq[tid] = g_qh[page][tid];
    __syncthreads();

    const float sh = g_hscale[page];
    const int r0 = blockIdx.x * 32 + warp * 4;
    const int4* w0 = (const int4*)(g_wq + (size_t)(r0 + 0) * (H / 4));
    const int4* w1 = (const int4*)(g_wq + (size_t)(r0 + 1) * (H / 4));
    const int4* w2 = (const int4*)(g_wq + (size_t)(r0 + 2) * (H / 4));
    const int4* w3 = (const int4*)(g_wq + (size_t)(r0 + 3) * (H / 4));

    int s0 = 0, s1 = 0, s2 = 0, s3 = 0;
    #pragma unroll
    for (int k = lane; k < H / 16; k += 32) {
        const int4 h = shq[k];
        int4 a;
        a = w0[k]; s0 = __dp4a(a.x, h.x, s0); s0 = __dp4a(a.y, h.y, s0);
                   s0 = __dp4a(a.z, h.z, s0); s0 = __dp4a(a.w, h.w, s0);
        a = w1[k]; s1 = __dp4a(a.x, h.x, s1); s1 = __dp4a(a.y, h.y, s1);
                   s1 = __dp4a(a.z, h.z, s1); s1 = __dp4a(a.w, h.w, s1);
        a = w2[k]; s2 = __dp4a(a.x, h.x, s2); s2 = __dp4a(a.y, h.y, s2);
                   s2 = __dp4a(a.z, h.z, s2); s2 = __dp4a(a.w, h.w, s2);
        a = w3[k]; s3 = __dp4a(a.x, h.x, s3); s3 = __dp4a(a.y, h.y, s3);
                   s3 = __dp4a(a.z, h.z, s3); s3 = __dp4a(a.w, h.w, s3);
    }
    s0 = __reduce_add_sync(0xffffffffu, s0);
    s1 = __reduce_add_sync(0xffffffffu, s1);
    s2 = __reduce_add_sync(0xffffffffu, s2);
    s3 = __reduce_add_sync(0xffffffffu, s3);
    if (lane == 0) {
        out_t[r0 + 0] = g_wscale[r0 + 0] * sh * (float)s0 + b_out[r0 + 0];
        out_t[r0 + 1] = g_wscale[r0 + 1] * sh * (float)s1 + b_out[r0 + 1];
        out_t[r0 + 2] = g_wscale[r0 + 2] * sh * (float)s2 + b_out[r0 + 2];
        out_t[r0 + 3] = g_wscale[r0 + 3] * sh * (float)s3 + b_out[r0 + 3];
    }
}

// ---------------- fused log-sum-exp + in-place log-softmax ----------------
__global__ void k_lsenorm(float* __restrict__ out_t)
{
    __shared__ float sm[1024];
    __shared__ float ss[1024];
    __shared__ float s_norm;
    const int tid = threadIdx.x;

    float m = -3.0e38f, s = 0.0f;
    float4* p = (float4*)out_t;
    for (int i = tid; i < VOCAB / 4; i += 1024) {
        const float4 v = p[i];
        const float vv[4] = {v.x, v.y, v.z, v.w};
        #pragma unroll
        for (int u = 0; u < 4; u++) {
            const float x = vv[u];
            if (x > m) { s = s * __expf(m - x) + 1.0f; m = x; }
            else       { s += __expf(x - m); }
        }
    }
    sm[tid] = m; ss[tid] = s;
    __syncthreads();
    for (int off = 512; off; off >>= 1) {
        if (tid < off) {
            const float m1 = sm[tid], s1 = ss[tid];
            const float m2 = sm[tid + off], s2 = ss[tid + off];
            if (m2 > m1) { sm[tid] = m2; ss[tid] = s2 + s1 * __expf(m1 - m2); }
            else         { ss[tid] = s1 + s2 * __expf(m2 - m1); }
        }
        __syncthreads();
    }
    if (tid == 0) s_norm = sm[0] + logf(ss[0]);
    __syncthreads();

    const float n = s_norm;
    for (int i = tid; i < VOCAB / 4; i += 1024) {
        float4 v = p[i];
        v.x -= n; v.y -= n; v.z -= n; v.w -= n;
        p[i] = v;
    }
}

// ---------------- host driver: two-stream pipeline (R6-proven topology) ----------------
extern "C" void kernel_launch(void* const* d_in, const int* in_sizes, int n_in,
                              void* d_out, int out_size)
{
    const float* vid   = (const float*)d_in[0];
    const float* w_ih1 = (const float*)d_in[1];
    const float* w_hh1 = (const float*)d_in[2];
    const float* b_ih1 = (const float*)d_in[3];
    const float* b_hh1 = (const float*)d_in[4];
    const float* w_ih2 = (const float*)d_in[5];
    const float* w_hh2 = (const float*)d_in[6];
    const float* b_ih2 = (const float*)d_in[7];
    const float* b_hh2 = (const float*)d_in[8];
    const float* emb   = (const float*)d_in[9];
    const float* w_out = (const float*)d_in[10];
    const float* b_out = (const float*)d_in[11];
    float* out = (float*)d_out;

    (void)in_sizes; (void)n_in; (void)out_size;

    // Host-side stream/event objects, created once on the first (non-capturing)
    // correctness call. Same topology as the R6 run that passed teardown checks.
    static cudaStream_t sB = nullptr;
    static cudaEvent_t  evMain[NSTEP], evB[NSTEP], evStart;
    if (!sB) {
        cudaStreamCreateWithFlags(&sB, cudaStreamNonBlocking);
        cudaEventCreateWithFlags(&evStart, cudaEventDisableTiming);
        for (int i = 0; i < NSTEP; i++) {
            cudaEventCreateWithFlags(&evMain[i], cudaEventDisableTiming);
            cudaEventCreateWithFlags(&evB[i],    cudaEventDisableTiming);
        }
    }

    k_init<<<1, 1>>>();

    // fork side stream B: build int8 w_out cache, overlapped with encode
    cudaEventRecord(evStart, 0);
    cudaStreamWaitEvent(sB, evStart, 0);
    k_quant_w<<<VOCAB / 32, 256, 0, sB>>>(w_out);

    // encode on main: lstm1(vid) -> h1[0]; lstm2([h1, 0-word], h=c=0) -> h2[0]
    k_lstm1_enc<<<H, 128>>>(w_ih1, vid, b_ih1, b_hh1);
    k_l2dep<<<H, 128>>>(w_ih2, b_ih2, b_hh2, /*p1=*/0, /*pout=*/0, /*use_part=*/0, /*c_zero=*/1);

    for (int t = 0; t < NSTEP; t++) {
        const int pin  = t & 1;
        const int pout = 1 - pin;
        float* out_t = out + (size_t)t * VOCAB;

        // page-reuse guard: h2prep(t) rewrites g_qh page used by logits(t-2)
        if (t >= 2) cudaStreamWaitEvent(0, evB[t - 2], 0);

        // fused concurrent matvecs: lstm1 split-K (2048 blocks) + lstm2-independent (1024 blocks)
        k_part<<<3 * H, 128>>>(w_hh1, w_ih2, w_hh2, emb, pin);
        // lstm1 gating
        k_l1fin<<<H / 128, 128>>>(b_ih1, b_hh1, pout);
        // lstm2 dependent part + gating
        k_l2dep<<<H, 128>>>(w_ih2, b_ih2, b_hh2, pout, pout, /*use_part=*/1, /*c_zero=*/0);
        // argmax + quantize h2
        k_h2prep<<<1, 1024>>>(pout);
        cudaEventRecord(evMain[t], 0);

        // stream B: output path, overlapped with next step's recurrence
        cudaStreamWaitEvent(sB, evMain[t], 0);
        k_logits_q<<<VOCAB / 32, 256, 0, sB>>>(b_out, pout, out_t);
        k_lsenorm<<<1, 1024, 0, sB>>>(out_t);
        cudaEventRecord(evB[t], sB);
    }

    // join side stream back into the origin stream before capture ends
    cudaStreamWaitEvent(0, evB[NSTEP - 1], 0);
}

// round 10
// speedup vs baseline: 2.6931x; 1.0933x over previous
#include <cuda_runtime.h>
#include <cstddef>
#include <cstdint>

#define H       1024
#define DV      4096
#define DW      512
#define VOCAB   32000
#define NSTEP   39      // MAX_LEN - 1
#define LG_TASKS 2000   // logits tasks per step, 16 rows each
#define LG_A     250    // logits tasks placed in phase A
#define NORM_TASKS 8    // norm-subtract tasks (4000 floats each)

// ---------------- persistent device state (no allocations allowed) ----------------
__device__ float g_h1[2][H];
__device__ float g_c1[H];
__device__ float g_h2[2][H];
__device__ float g_c2[H];
__device__ float g_p2[4 * H];             // lstm2 independent-part partials

__device__ int   g_wq[VOCAB * (H / 4)];   // int8 w_out cache (packed)
__device__ float g_wscale[VOCAB];

__device__ float g_lmax[2][LG_TASKS];     // per-logits-task lse partials (page = step&1)
__device__ float g_lsum[2][LG_TASKS];
__device__ float g_norm[2];

__device__ unsigned g_bar_count;
__device__ unsigned g_bar_gen;

__device__ __forceinline__ float sigmoidf_(float x) { return 1.0f / (1.0f + expf(-x)); }

__global__ void k_init() { g_bar_count = 0; g_bar_gen = 0; }

// ---------------- grid barrier: sense-reversing, all blocks co-resident ----------------
__device__ __forceinline__ void gbar(unsigned G)
{
    __syncthreads();
    if (threadIdx.x == 0) {
        __threadfence();
        const unsigned gen = *(volatile unsigned*)&g_bar_gen;
        if (atomicAdd(&g_bar_count, 1u) == G - 1u) {
            atomicExch(&g_bar_count, 0u);
            __threadfence();
            atomicAdd(&g_bar_gen, 1u);
        } else {
            while (*(volatile unsigned*)&g_bar_gen == gen) __nanosleep(64);
        }
        __threadfence();
    }
    __syncthreads();
}

// ---------------- quantize w_out rows to int8 (once per launch) ----------------
__global__ void k_quant_w(const float* __restrict__ w)
{
    const int warp = threadIdx.x >> 5;
    const int lane = threadIdx.x & 31;
    const int row0 = blockIdx.x * 32 + warp * 4;

    for (int rr = 0; rr < 4; rr++) {
        const int row = row0 + rr;
        const float4* wr = (const float4*)(w + (size_t)row * H);
        float4 v[8];
        float m = 0.0f;
        #pragma unroll
        for (int i = 0; i < 8; i++) {
            v[i] = wr[lane + 32 * i];
            m = fmaxf(m, fmaxf(fmaxf(fabsf(v[i].x), fabsf(v[i].y)),
                               fmaxf(fabsf(v[i].z), fabsf(v[i].w))));
        }
        #pragma unroll
        for (int o = 16; o; o >>= 1) m = fmaxf(m, __shfl_xor_sync(0xffffffffu, m, o));
        const float inv = (m > 0.0f) ? 127.0f / m : 0.0f;
        #pragma unroll
        for (int i = 0; i < 8; i++) {
            const int a = (int)rintf(v[i].x * inv);
            const int b = (int)rintf(v[i].y * inv);
            const int c = (int)rintf(v[i].z * inv);
            const int d = (int)rintf(v[i].w * inv);
            g_wq[row * (H / 4) + lane + 32 * i] =
                (a & 0xFF) | ((b & 0xFF) << 8) | ((c & 0xFF) << 16) | ((d & 0xFF) << 24);
        }
        if (lane == 0) g_wscale[row] = m / 127.0f;
    }
}

// ---------------- LSTM1 encode (h=c=0, x=vid) -> h1[0], c1 ----------------
__global__ void k_lstm1_enc(const float* __restrict__ w_ih, const float* __restrict__ x,
                            const float* __restrict__ b_ih, const float* __restrict__ b_hh)
{
    __shared__ float sx[DV];
    __shared__ float red[4];
    const int j = blockIdx.x, tid = threadIdx.x, warp = tid >> 5, lane = tid & 31;

    for (int i = tid; i < DV; i += 128) sx[i] = x[i];
    __syncthreads();

    const int r = warp * H + j;
    const float4* wr = (const float4*)(w_ih + (size_t)r * DV);
    const float4* xv = (const float4*)sx;
    float s = 0.0f;
    #pragma unroll
    for (int k0 = 0; k0 < DV / 4; k0 += 256) {
        float4 a[8];
        #pragma unroll
        for (int u = 0; u < 8; u++) a[u] = wr[k0 + lane + 32 * u];
        #pragma unroll
        for (int u = 0; u < 8; u++) {
            const float4 b = xv[k0 + lane + 32 * u];
            s += a[u].x * b.x + a[u].y * b.y + a[u].z * b.z + a[u].w * b.w;
        }
    }
    #pragma unroll
    for (int o = 16; o; o >>= 1) s += __shfl_xor_sync(0xffffffffu, s, o);
    if (lane == 0) red[warp] = s + b_ih[r] + b_hh[r];
    __syncthreads();

    if (tid == 0) {
        const float gi = red[0], gf = red[1], gg = red[2], go = red[3];
        const float cn = sigmoidf_(gi) * tanhf(gg);
        g_c1[j]    = cn;
        g_h1[0][j] = sigmoidf_(go) * tanhf(cn);
    }
}

// ---------------- LSTM2 encode: input [h1(enc), zeros], h=c=0 -> h2[0], c2 ----------------
__global__ void k_l2enc(const float* __restrict__ w_ih,
                        const float* __restrict__ b_ih, const float* __restrict__ b_hh)
{
    __shared__ float sh[H];
    __shared__ float red[4];
    const int j = blockIdx.x, tid = threadIdx.x, warp = tid >> 5, lane = tid & 31;

    for (int i = tid; i < H; i += 128) sh[i] = g_h1[0][i];
    __syncthreads();

    const int r = warp * H + j;
    const float4* wr = (const float4*)(w_ih + (size_t)r * (H + DW));
    const float4* hv = (const float4*)sh;
    float4 a[8];
    #pragma unroll
    for (int u = 0; u < 8; u++) a[u] = wr[lane + 32 * u];
    float s = 0.0f;
    #pragma unroll
    for (int u = 0; u < 8; u++) {
        const float4 b = hv[lane + 32 * u];
        s += a[u].x * b.x + a[u].y * b.y + a[u].z * b.z + a[u].w * b.w;
    }
    #pragma unroll
    for (int o = 16; o; o >>= 1) s += __shfl_xor_sync(0xffffffffu, s, o);
    if (lane == 0) red[warp] = s + b_ih[r] + b_hh[r];
    __syncthreads();

    if (tid == 0) {
        const float gi = red[0], gf = red[1], gg = red[2], go = red[3];
        const float cn = sigmoidf_(gi) * tanhf(gg);   // c_prev = 0
        g_c2[j]    = cn;
        g_h2[0][j] = sigmoidf_(go) * tanhf(cn);
    }
}

// ---------------- helpers ----------------
__device__ __forceinline__ int pack4(float4 v, float inv)
{
    const int a = (int)rintf(v.x * inv);
    const int b = (int)rintf(v.y * inv);
    const int c = (int)rintf(v.z * inv);
    const int d = (int)rintf(v.w * inv);
    return (a & 0xFF) | ((b & 0xFF) << 8) | ((c & 0xFF) << 16) | ((d & 0xFF) << 24);
}

// ---------------- the persistent decode kernel ----------------
__global__ void __launch_bounds__(128, 8)
k_decode(const float* __restrict__ w_hh1,
         const float* __restrict__ w_ih2, const float* __restrict__ w_hh2,
         const float* __restrict__ b_ih1, const float* __restrict__ b_hh1,
         const float* __restrict__ b_ih2, const float* __restrict__ b_hh2,
         const float* __restrict__ emb,  const float* __restrict__ b_out,
         float* __restrict__ out, unsigned G)
{
    __shared__ float sv[H + DW];      // staging for matvec inputs
    __shared__ int4  qh4[H / 16];     // per-block quantized h2 (persists across phases of a step)
    __shared__ float red[4];
    __shared__ float s_m[128];
    __shared__ int   s_i[128];
    __shared__ float s_a[128];
    __shared__ float s_rows[16];
    __shared__ float s_hscale;
    __shared__ int   s_gidx;

    const unsigned b   = blockIdx.x;
    const int tid  = threadIdx.x;
    const int warp = tid >> 5;
    const int lane = tid & 31;

    // ---------- per-phase task bodies ----------
    auto l2ind_task = [&](int j, int pin) {
        // stage h2[pin] + emb[idx]
        const float4* h2p = (const float4*)g_h2[pin];
        for (int k = tid; k < H / 4; k += 128) ((float4*)sv)[k] = __ldcg(h2p + k);
        const float4* ev = (const float4*)(emb + (size_t)s_gidx * DW);
        for (int k = tid; k < DW / 4; k += 128) ((float4*)sv)[H / 4 + k] = ev[k];
        __syncthreads();

        const int r = warp * H + j;
        const float4* whh  = (const float4*)(w_hh2 + (size_t)r * H);
        const float4* wemb = (const float4*)(w_ih2 + (size_t)r * (H + DW) + H);
        const float4* hv   = (const float4*)sv;
        float s = 0.0f;
        {
            float4 a[8];
            #pragma unroll
            for (int u = 0; u < 8; u++) a[u] = whh[lane + 32 * u];
            #pragma unroll
            for (int u = 0; u < 8; u++) {
                const float4 x = hv[lane + 32 * u];
                s += a[u].x * x.x + a[u].y * x.y + a[u].z * x.z + a[u].w * x.w;
            }
        }
        {
            float4 e[4];
            #pragma unroll
            for (int u = 0; u < 4; u++) e[u] = wemb[lane + 32 * u];
            #pragma unroll
            for (int u = 0; u < 4; u++) {
                const float4 x = hv[H / 4 + lane + 32 * u];
                s += e[u].x * x.x + e[u].y * x.y + e[u].z * x.z + e[u].w * x.w;
            }
        }
        #pragma unroll
        for (int o = 16; o; o >>= 1) s += __shfl_xor_sync(0xffffffffu, s, o);
        if (lane == 0) g_p2[r] = s;
        __syncthreads();
    };

    auto l1_task = [&](int j, int pin, int pout) {
        const float4* h1p = (const float4*)g_h1[pin];
        for (int k = tid; k < H / 4; k += 128) ((float4*)sv)[k] = __ldcg(h1p + k);
        __syncthreads();

        const int r = warp * H + j;
        const float4* wr = (const float4*)(w_hh1 + (size_t)r * H);
        const float4* hv = (const float4*)sv;
        float4 a[8];
        #pragma unroll
        for (int u = 0; u < 8; u++) a[u] = wr[lane + 32 * u];
        float s = 0.0f;
        #pragma unroll
        for (int u = 0; u < 8; u++) {
            const float4 x = hv[lane + 32 * u];
            s += a[u].x * x.x + a[u].y * x.y + a[u].z * x.z + a[u].w * x.w;
        }
        #pragma unroll
        for (int o = 16; o; o >>= 1) s += __shfl_xor_sync(0xffffffffu, s, o);
        if (lane == 0) red[warp] = s + b_ih1[r] + b_hh1[r];
        __syncthreads();
        if (tid == 0) {
            const float gi = red[0], gf = red[1], gg = red[2], go = red[3];
            const float cn = sigmoidf_(gf) * __ldcg(&g_c1[j]) + sigmoidf_(gi) * tanhf(gg);
            g_c1[j]        = cn;
            g_h1[pout][j]  = sigmoidf_(go) * tanhf(cn);
        }
        __syncthreads();
    };

    auto dep_task = [&](int j, int pout) {
        const float4* h1p = (const float4*)g_h1[pout];
        for (int k = tid; k < H / 4; k += 128) ((float4*)sv)[k] = __ldcg(h1p + k);
        __syncthreads();

        const int r = warp * H + j;
        const float4* wr = (const float4*)(w_ih2 + (size_t)r * (H + DW));
        const float4* hv = (const float4*)sv;
        float4 a[8];
        #pragma unroll
        for (int u = 0; u < 8; u++) a[u] = wr[lane + 32 * u];
        float s = 0.0f;
        #pragma unroll
        for (int u = 0; u < 8; u++) {
            const float4 x = hv[lane + 32 * u];
            s += a[u].x * x.x + a[u].y * x.y + a[u].z * x.z + a[u].w * x.w;
        }
        #pragma unroll
        for (int o = 16; o; o >>= 1) s += __shfl_xor_sync(0xffffffffu, s, o);
        if (lane == 0) red[warp] = s + __ldcg(&g_p2[r]) + b_ih2[r] + b_hh2[r];
        __syncthreads();
        if (tid == 0) {
            const float gi = red[0], gf = red[1], gg = red[2], go = red[3];
            const float cn = sigmoidf_(gf) * __ldcg(&g_c2[j]) + sigmoidf_(gi) * tanhf(gg);
            g_c2[j]        = cn;
            g_h2[pout][j]  = sigmoidf_(go) * tanhf(cn);
        }
        __syncthreads();
    };

    auto logits_task = [&](int s_step, int lt) {
        // 16 rows, int8 dp4a against smem qh; raw logits to out; lse partial to g_l*
        const int page = s_step & 1;
        const float hs = s_hscale;
        float* out_t = out + (size_t)s_step * VOCAB;
        const int r0 = lt * 16 + warp * 4;
        const int4* w0 = (const int4*)(g_wq + (size_t)(r0 + 0) * (H / 4));
        const int4* w1 = (const int4*)(g_wq + (size_t)(r0 + 1) * (H / 4));
        const int4* w2 = (const int4*)(g_wq + (size_t)(r0 + 2) * (H / 4));
        const int4* w3 = (const int4*)(g_wq + (size_t)(r0 + 3) * (H / 4));
        int s0 = 0, s1 = 0, s2 = 0, s3 = 0;
        #pragma unroll
        for (int k = lane; k < H / 16; k += 32) {
            const int4 h = qh4[k];
            int4 a;
            a = w0[k]; s0 = __dp4a(a.x, h.x, s0); s0 = __dp4a(a.y, h.y, s0);
                       s0 = __dp4a(a.z, h.z, s0); s0 = __dp4a(a.w, h.w, s0);
            a = w1[k]; s1 = __dp4a(a.x, h.x, s1); s1 = __dp4a(a.y, h.y, s1);
                       s1 = __dp4a(a.z, h.z, s1); s1 = __dp4a(a.w, h.w, s1);
            a = w2[k]; s2 = __dp4a(a.x, h.x, s2); s2 = __dp4a(a.y, h.y, s2);
                       s2 = __dp4a(a.z, h.z, s2); s2 = __dp4a(a.w, h.w, s2);
            a = w3[k]; s3 = __dp4a(a.x, h.x, s3); s3 = __dp4a(a.y, h.y, s3);
                       s3 = __dp4a(a.z, h.z, s3); s3 = __dp4a(a.w, h.w, s3);
        }
        s0 = __reduce_add_sync(0xffffffffu, s0);
        s1 = __reduce_add_sync(0xffffffffu, s1);
        s2 = __reduce_add_sync(0xffffffffu, s2);
        s3 = __reduce_add_sync(0xffffffffu, s3);
        if (lane == 0) {
            const float v0 = g_wscale[r0 + 0] * hs * (float)s0 + b_out[r0 + 0];
            const float v1 = g_wscale[r0 + 1] * hs * (float)s1 + b_out[r0 + 1];
            const float v2 = g_wscale[r0 + 2] * hs * (float)s2 + b_out[r0 + 2];
            const float v3 = g_wscale[r0 + 3] * hs * (float)s3 + b_out[r0 + 3];
            out_t[r0 + 0] = v0; out_t[r0 + 1] = v1;
            out_t[r0 + 2] = v2; out_t[r0 + 3] = v3;
            s_rows[warp * 4 + 0] = v0; s_rows[warp * 4 + 1] = v1;
            s_rows[warp * 4 + 2] = v2; s_rows[warp * 4 + 3] = v3;
        }
        __syncthreads();
        if (tid == 0) {
            float m = s_rows[0];
            #pragma unroll
            for (int u = 1; u < 16; u++) m = fmaxf(m, s_rows[u]);
            float sm = 0.0f;
            #pragma unroll
            for (int u = 0; u < 16; u++) sm += expf(s_rows[u] - m);
            g_lmax[page][lt] = m;
            g_lsum[page][lt] = sm;
        }
        __syncthreads();
    };

    auto combine_task = [&](int s_step) {
        const int page = s_step & 1;
        float m = -3.0e38f, sum = 0.0f;
        const int k0 = tid * 16;
        for (int k = k0; k < k0 + 16 && k < LG_TASKS; k++) {
            const float m2 = __ldcg(&g_lmax[page][k]);
            const float s2 = __ldcg(&g_lsum[page][k]);
            if (m2 > m) { sum = sum * __expf(m - m2) + s2; m = m2; }
            else        { sum += s2 * __expf(m2 - m); }
        }
        s_m[tid] = m; s_a[tid] = sum;
        __syncthreads();
        for (int off = 64; off; off >>= 1) {
            if (tid < off) {
                const float m1 = s_m[tid], sA = s_a[tid];
                const float m2 = s_m[tid + off], sB = s_a[tid + off];
                if (m2 > m1) { s_m[tid] = m2; s_a[tid] = sB + sA * __expf(m1 - m2); }
                else         { s_a[tid] = sA + sB * __expf(m2 - m1); }
            }
            __syncthreads();
        }
        if (tid == 0) g_norm[page] = s_m[0] + logf(s_a[0]);
        __syncthreads();
    };

    auto norm_task = [&](int s_step, int k) {
        const float n = __ldcg(&g_norm[s_step & 1]);
        float4* p = (float4*)(out + (size_t)s_step * VOCAB) + k * 1000;
        for (int i = tid; i < 1000; i += 128) {
            float4 v = __ldcg(p + i);
            v.x -= n; v.y -= n; v.z -= n; v.w -= n;
            p[i] = v;
        }
    };

    auto preamble = [&](int pin, int t) {
        // per-block: argmax + absmax + int8 quant of h2[pin] into smem
        const float4* h2p = (const float4*)g_h2[pin];
        const float4 va = __ldcg(h2p + tid);
        const float4 vb = __ldcg(h2p + 128 + tid);
        float am = fmaxf(fmaxf(fabsf(va.x), fabsf(va.y)), fmaxf(fabsf(va.z), fabsf(va.w)));
        am = fmaxf(am, fmaxf(fmaxf(fabsf(vb.x), fabsf(vb.y)), fmaxf(fabsf(vb.z), fabsf(vb.w))));
        float bm = va.x; int bi = 4 * tid;
        if (va.y > bm) { bm = va.y; bi = 4 * tid + 1; }
        if (va.z > bm) { bm = va.z; bi = 4 * tid + 2; }
        if (va.w > bm) { bm = va.w; bi = 4 * tid + 3; }
        if (vb.x > bm) { bm = vb.x; bi = 512 + 4 * tid; }
        if (vb.y > bm) { bm = vb.y; bi = 512 + 4 * tid + 1; }
        if (vb.z > bm) { bm = vb.z; bi = 512 + 4 * tid + 2; }
        if (vb.w > bm) { bm = vb.w; bi = 512 + 4 * tid + 3; }
        s_m[tid] = bm; s_i[tid] = bi; s_a[tid] = am;
        __syncthreads();
        for (int off = 64; off; off >>= 1) {
            if (tid < off) {
                const float v2 = s_m[tid + off]; const int i2 = s_i[tid + off];
                if (v2 > s_m[tid] || (v2 == s_m[tid] && i2 < s_i[tid])) { s_m[tid] = v2; s_i[tid] = i2; }
                s_a[tid] = fmaxf(s_a[tid], s_a[tid + off]);
            }
            __syncthreads();
        }
        if (tid == 0) {
            s_hscale = s_a[0] / 127.0f;
            s_gidx = (t == 0) ? 0 : s_i[0];
        }
        __syncthreads();
        const float inv = (s_a[0] > 0.0f) ? 127.0f / s_a[0] : 0.0f;
        ((int*)qh4)[tid]       = pack4(va, inv);
        ((int*)qh4)[128 + tid] = pack4(vb, inv);
        __syncthreads();
    };

    // ================= main decode loop =================
    for (int t = 0; t < NSTEP; t++) {
        const int pin = t & 1, pout = 1 - pin;

        preamble(pin, t);

        // ---- phase A: lstm2-independent + lstm1(full+gate) + logits(t-1) chunk + combine(t-2)
        {
            const unsigned nlog = (t >= 1) ? LG_A : 0;
            const unsigned NA = 2048u + nlog + ((t >= 2) ? 1u : 0u);
            for (unsigned i = b; i < NA; i += G) {
                if (i < 1024u)            l2ind_task((int)i, pin);
                else if (i < 2048u)       l1_task((int)i - 1024, pin, pout);
                else if (i < 2048u + nlog) logits_task(t - 1, (int)(i - 2048u));
                else                       combine_task(t - 2);
            }
        }
        gbar(G);

        // ---- phase B: lstm2-dependent (gates h2) + logits(t-1) rest + norm(t-2)
        {
            const unsigned nlog = (t >= 1) ? (LG_TASKS - LG_A) : 0;
            const unsigned NB = 1024u + nlog + ((t >= 2) ? (unsigned)NORM_TASKS : 0u);
            for (unsigned i = b; i < NB; i += G) {
                if (i < 1024u)             dep_task((int)i, pout);
                else if (i < 1024u + nlog) logits_task(t - 1, LG_A + (int)(i - 1024u));
                else                       norm_task(t - 2, (int)(i - 1024u - nlog));
            }
        }
        gbar(G);
    }

    // ================= drain =================
    // D1: logits(38) all tasks (quantize h2(38) first) + combine(37)
    preamble(NSTEP & 1, NSTEP);
    for (unsigned i = b; i < (unsigned)LG_TASKS + 1u; i += G) {
        if (i < (unsigned)LG_TASKS) logits_task(NSTEP - 1, (int)i);
        else                        combine_task(NSTEP - 2);
    }
    gbar(G);
    // D2: norm(37) + combine(38)
    for (unsigned i = b; i < (unsigned)NORM_TASKS + 1u; i += G) {
        if (i < (unsigned)NORM_TASKS) norm_task(NSTEP - 2, (int)i);
        else                          combine_task(NSTEP - 1);
    }
    gbar(G);
    // D3: norm(38)
    for (unsigned i = b; i < (unsigned)NORM_TASKS; i += G) norm_task(NSTEP - 1, (int)i);
}

// ---------------- host driver: single stream, 5 launches, trivially capturable ----------------
extern "C" void kernel_launch(void* const* d_in, const int* in_sizes, int n_in,
                              void* d_out, int out_size)
{
    const float* vid   = (const float*)d_in[0];
    const float* w_ih1 = (const float*)d_in[1];
    const float* w_hh1 = (const float*)d_in[2];
    const float* b_ih1 = (const float*)d_in[3];
    const float* b_hh1 = (const float*)d_in[4];
    const float* w_ih2 = (const float*)d_in[5];
    const float* w_hh2 = (const float*)d_in[6];
    const float* b_ih2 = (const float*)d_in[7];
    const float* b_hh2 = (const float*)d_in[8];
    const float* emb   = (const float*)d_in[9];
    const float* w_out = (const float*)d_in[10];
    const float* b_out = (const float*)d_in[11];
    float* out = (float*)d_out;

    (void)in_sizes; (void)n_in; (void)out_size;

    static int smCount = 0;
    if (smCount == 0) cudaDeviceGetAttribute(&smCount, cudaDevAttrMultiProcessorCount, 0);
    const unsigned G = (unsigned)smCount * 8u;   // co-resident by __launch_bounds__(128, 8)

    k_init<<<1, 1>>>();
    k_quant_w<<<VOCAB / 32, 256>>>(w_out);
    k_lstm1_enc<<<H, 128>>>(w_ih1, vid, b_ih1, b_hh1);
    k_l2enc<<<H, 128>>>(w_ih2, b_ih2, b_hh2);
    k_decode<<<G, 128>>>(w_hh1, w_ih2, w_hh2, b_ih1, b_hh1, b_ih2, b_hh2,
                         emb, b_out, out, G);
}